// round 3
// baseline (speedup 1.0000x reference)
#include <cuda_runtime.h>
#include <cstdint>

// ---------------- scratch (device globals; no runtime allocation) ----------------
__device__ float g_xn  [8u*4096u*256u];         // LayerNorm output  [B*L, C]
__device__ float g_qkv [8u*4096u*768u];         // QKV               [B*L, 3C]
__device__ float g_xcat[8u*256u*4096u];         // pre-proj image    [B, C, H*W]
__device__ float g_attn_fb[2u*128u*4u*256u*256u]; // fallback attn store if d_out lacks space

// ---------------- Kernel 1: transpose + LayerNorm ----------------
// x [B, C, H, W] -> g_xn [B*L, C], LN over C. Block: 32 tokens x 256 channels.
__global__ void ln_kernel(const float* __restrict__ x,
                          const float* __restrict__ gam,
                          const float* __restrict__ bet) {
    __shared__ float s[32][257];
    int bb    = blockIdx.x >> 7;          // batch
    int lbase = (blockIdx.x & 127) << 5;  // token base (32 tokens per block)
    int tx = threadIdx.x, ty = threadIdx.y;
    const float* xb = x + (size_t)bb * 256 * 4096;
    #pragma unroll
    for (int i = 0; i < 8; ++i) {
        int cc = ty + (i << 5);
        s[tx][cc] = xb[(size_t)cc * 4096 + lbase + tx];  // coalesced in tx
    }
    __syncthreads();
    // warp ty handles token (lbase+ty)
    float v[8], sum = 0.f, sq = 0.f;
    #pragma unroll
    for (int i = 0; i < 8; ++i) {
        v[i] = s[ty][tx + (i << 5)];
        sum += v[i]; sq += v[i] * v[i];
    }
    #pragma unroll
    for (int o = 16; o; o >>= 1) {
        sum += __shfl_xor_sync(0xffffffffu, sum, o);
        sq  += __shfl_xor_sync(0xffffffffu, sq,  o);
    }
    float mean = sum * (1.f / 256.f);
    float var  = sq  * (1.f / 256.f) - mean * mean;
    float rstd = rsqrtf(var + 1e-4f);
    float* op = g_xn + (size_t)(bb * 4096 + lbase + ty) * 256;
    #pragma unroll
    for (int i = 0; i < 8; ++i) {
        int cc = tx + (i << 5);
        op[cc] = (v[i] - mean) * rstd * gam[cc] + bet[cc];
    }
}

// ---------------- Kernel 2: QKV GEMM ----------------
// g_qkv[m,n] = sum_k g_xn[m,k] * W[n,k];  M=32768, N=768, K=256
__global__ __launch_bounds__(256) void gemm_qkv(const float* __restrict__ W) {
    __shared__ float As[16][128];
    __shared__ float Bs[16][128];
    int n0 = blockIdx.x << 7;
    int m0 = blockIdx.y << 7;
    int tid = threadIdx.x;
    int tm = (tid >> 4) << 3;
    int tn = (tid & 15) << 3;
    float acc[8][8];
    #pragma unroll
    for (int i = 0; i < 8; ++i)
        #pragma unroll
        for (int j = 0; j < 8; ++j) acc[i][j] = 0.f;

    for (int k0 = 0; k0 < 256; k0 += 16) {
        #pragma unroll
        for (int i = 0; i < 2; ++i) {
            int idx = tid + (i << 8);
            int r   = idx >> 2;
            int kq  = (idx & 3) << 2;
            float4 va = *(const float4*)(g_xn + (size_t)(m0 + r) * 256 + k0 + kq);
            As[kq+0][r]=va.x; As[kq+1][r]=va.y; As[kq+2][r]=va.z; As[kq+3][r]=va.w;
            float4 vb = *(const float4*)(W + (size_t)(n0 + r) * 256 + k0 + kq);
            Bs[kq+0][r]=vb.x; Bs[kq+1][r]=vb.y; Bs[kq+2][r]=vb.z; Bs[kq+3][r]=vb.w;
        }
        __syncthreads();
        #pragma unroll
        for (int k = 0; k < 16; ++k) {
            float a[8], b[8];
            *(float4*)&a[0] = *(const float4*)&As[k][tm];
            *(float4*)&a[4] = *(const float4*)&As[k][tm + 4];
            *(float4*)&b[0] = *(const float4*)&Bs[k][tn];
            *(float4*)&b[4] = *(const float4*)&Bs[k][tn + 4];
            #pragma unroll
            for (int i = 0; i < 8; ++i)
                #pragma unroll
                for (int j = 0; j < 8; ++j)
                    acc[i][j] = fmaf(a[i], b[j], acc[i][j]);
        }
        __syncthreads();
    }
    #pragma unroll
    for (int i = 0; i < 8; ++i) {
        float* cp = g_qkv + (size_t)(m0 + tm + i) * 768 + n0 + tn;
        float4 c0 = {acc[i][0], acc[i][1], acc[i][2], acc[i][3]};
        float4 c1 = {acc[i][4], acc[i][5], acc[i][6], acc[i][7]};
        *(float4*)cp = c0; *(float4*)(cp + 4) = c1;
    }
}

// ---------------- Kernel 3: stripe-window attention + LePE ----------------
// One block per (branch, window, head). 256 threads; thread t owns query row t.
__global__ __launch_bounds__(256) void attn_kernel(
        const float* __restrict__ lw1, const float* __restrict__ lb1,
        const float* __restrict__ lw2, const float* __restrict__ lb2,
        float* attnOut0, float* attnOut1) {
    extern __shared__ float sm[];
    float* Ks    = sm;          // 8192 floats  [s][ci]
    float* Vs    = sm + 8192;   // 8192
    float* stage = sm + 16384;  // 256*17
    float* rinv  = sm + 20736;  // 256
    float* wleT  = sm + 20992;  // 9*32  [k][ci]
    float* blep  = sm + 21280;  // 32
    const float4* Ks4 = (const float4*)Ks;
    const float4* Vs4 = (const float4*)Vs;

    int blk    = blockIdx.x;
    int branch = blk >> 9;
    int rem    = blk & 511;
    int bw     = rem >> 2;
    int head   = rem & 3;
    int bb     = bw >> 4;
    int widx   = bw & 15;     // branch0: stripe col index; branch1: stripe row index
    int tid    = threadIdx.x;
    int cbase  = branch * 128 + head;

    // cooperative K/V gather into smem (window layout)
    for (int e = tid; e < 8192; e += 256) {
        int s = e >> 5, ci = e & 31;
        int l = (branch == 0) ? ((s >> 2) * 64 + widx * 4 + (s & 3))
                              : ((widx * 4 + (s >> 6)) * 64 + (s & 63));
        const float* rp = g_qkv + (size_t)(bb * 4096 + l) * 768 + cbase + ci * 4;
        Ks[e] = rp[256];
        Vs[e] = rp[512];
    }
    const float* lw = branch ? lw2 : lw1;
    const float* lb = branch ? lb2 : lb1;
    for (int e = tid; e < 288; e += 256) {        // grid-stride: covers all 288 entries
        int kk = e >> 5, ci = e & 31;
        wleT[e] = lw[(ci * 4 + head) * 9 + kk];
    }
    if (tid < 32) blep[tid] = lb[tid * 4 + head];

    // own query row (pre-scaled by 1/sqrt(64))
    int lq = (branch == 0) ? ((tid >> 2) * 64 + widx * 4 + (tid & 3))
                           : ((widx * 4 + (tid >> 6)) * 64 + (tid & 63));
    const float* qp = g_qkv + (size_t)(bb * 4096 + lq) * 768 + cbase;
    float4 q4[8];
    #pragma unroll
    for (int u = 0; u < 8; ++u) {
        q4[u].x = qp[(u * 4 + 0) * 4] * 0.125f;
        q4[u].y = qp[(u * 4 + 1) * 4] * 0.125f;
        q4[u].z = qp[(u * 4 + 2) * 4] * 0.125f;
        q4[u].w = qp[(u * 4 + 3) * 4] * 0.125f;
    }
    __syncthreads();

    float* attnRow = (branch ? (attnOut1 ? attnOut1 : g_attn_fb + 33554432)
                             : (attnOut0 ? attnOut0 : g_attn_fb))
                     + (size_t)(bw * 4 + head) * 65536;

    float4 oac[8];
    #pragma unroll
    for (int u = 0; u < 8; ++u) oac[u] = make_float4(0.f, 0.f, 0.f, 0.f);
    float ssum = 0.f;

    // fused: logits -> exp -> (sum, o += e*v), e written via smem staging (coalesced)
    for (int ch = 0; ch < 16; ++ch) {
        float ebuf[16];
        #pragma unroll
        for (int jj = 0; jj < 16; ++jj) {
            int j = (ch << 4) + jj;
            const float4* kr = Ks4 + j * 8;
            float d = 0.f;
            #pragma unroll
            for (int u = 0; u < 8; ++u) {
                float4 kk = kr[u];
                d = fmaf(q4[u].x, kk.x, d);
                d = fmaf(q4[u].y, kk.y, d);
                d = fmaf(q4[u].z, kk.z, d);
                d = fmaf(q4[u].w, kk.w, d);
            }
            float e = __expf(d);   // logits are O(0.1) here: no max-shift needed
            ssum += e;
            ebuf[jj] = e;
            const float4* vr = Vs4 + j * 8;
            #pragma unroll
            for (int u = 0; u < 8; ++u) {
                float4 vv = vr[u];
                oac[u].x = fmaf(e, vv.x, oac[u].x);
                oac[u].y = fmaf(e, vv.y, oac[u].y);
                oac[u].z = fmaf(e, vv.z, oac[u].z);
                oac[u].w = fmaf(e, vv.w, oac[u].w);
            }
        }
        #pragma unroll
        for (int jj = 0; jj < 16; ++jj) stage[tid * 17 + jj] = ebuf[jj];
        __syncthreads();
        #pragma unroll
        for (int i = 0; i < 16; ++i) {
            int idx = tid + (i << 8);
            int ss = idx >> 4, jj = idx & 15;
            attnRow[ss * 256 + (ch << 4) + jj] = stage[ss * 17 + jj];
        }
        __syncthreads();
    }

    // normalize attn in place (coalesced float4 pass), row scale from smem
    float is = 1.f / ssum;
    rinv[tid] = is;
    __syncthreads();
    float4* a4 = (float4*)attnRow;
    for (int i = 0; i < 64; ++i) {
        int idx = tid + (i << 8);
        float r = rinv[idx >> 6];
        float4 vv = a4[idx];
        vv.x *= r; vv.y *= r; vv.z *= r; vv.w *= r;
        a4[idx] = vv;
    }

    // LePE (depthwise 3x3 on window image) + epilogue
    int y, x, Wimg, Himg;
    if (branch == 0) { y = tid >> 2; x = tid & 3;  Wimg = 4;  Himg = 64; }
    else             { y = tid >> 6; x = tid & 63; Wimg = 64; Himg = 4;  }
    float4 lep[8];
    #pragma unroll
    for (int u = 0; u < 8; ++u) lep[u] = *(const float4*)&blep[u * 4];
    #pragma unroll
    for (int ky = 0; ky < 3; ++ky) {
        int yy = y + ky - 1;
        if (yy < 0 || yy >= Himg) continue;
        #pragma unroll
        for (int kx = 0; kx < 3; ++kx) {
            int xx = x + kx - 1;
            if (xx < 0 || xx >= Wimg) continue;
            int sp = yy * Wimg + xx;
            const float4* vv = Vs4 + sp * 8;
            const float* wrow = wleT + (ky * 3 + kx) * 32;
            #pragma unroll
            for (int u = 0; u < 8; ++u) {
                float4 w4 = *(const float4*)&wrow[u * 4];
                float4 vu = vv[u];
                lep[u].x = fmaf(w4.x, vu.x, lep[u].x);
                lep[u].y = fmaf(w4.y, vu.y, lep[u].y);
                lep[u].z = fmaf(w4.z, vu.z, lep[u].z);
                lep[u].w = fmaf(w4.w, vu.w, lep[u].w);
            }
        }
    }
    int row, col;
    if (branch == 0) { row = y;            col = widx * 4 + x; }
    else             { row = widx * 4 + y; col = x;            }
    int pos = row * 64 + col;
    #pragma unroll
    for (int u = 0; u < 8; ++u) {
        float o0 = oac[u].x * is + lep[u].x;
        float o1 = oac[u].y * is + lep[u].y;
        float o2 = oac[u].z * is + lep[u].z;
        float o3 = oac[u].w * is + lep[u].w;
        int ci0 = u * 4;
        g_xcat[(size_t)(bb * 256 + branch * 128 + (ci0 + 0) * 4 + head) * 4096 + pos] = o0;
        g_xcat[(size_t)(bb * 256 + branch * 128 + (ci0 + 1) * 4 + head) * 4096 + pos] = o1;
        g_xcat[(size_t)(bb * 256 + branch * 128 + (ci0 + 2) * 4 + head) * 4096 + pos] = o2;
        g_xcat[(size_t)(bb * 256 + branch * 128 + (ci0 + 3) * 4 + head) * 4096 + pos] = o3;
    }
}

// ---------------- Kernel 4: 1x1 projection GEMM ----------------
// out[(b*256+n)*4096+p] = sum_k g_xcat[(b*256+k)*4096+p] * PW[n*256+k] + PB[n]
__global__ __launch_bounds__(256) void gemm_proj(const float* __restrict__ PW,
                                                 const float* __restrict__ PB,
                                                 float* __restrict__ out) {
    __shared__ float As[16][128];   // [k][p]
    __shared__ float Bs[16][128];   // [k][n]
    int n0 = blockIdx.x << 7;
    int mg = blockIdx.y << 7;
    int bb = mg >> 12;
    int p0 = mg & 4095;
    int tid = threadIdx.x;
    int tm = (tid >> 4) << 3;   // p
    int tn = (tid & 15) << 3;   // n
    float acc[8][8];
    #pragma unroll
    for (int i = 0; i < 8; ++i)
        #pragma unroll
        for (int j = 0; j < 8; ++j) acc[i][j] = 0.f;

    for (int k0 = 0; k0 < 256; k0 += 16) {
        #pragma unroll
        for (int i = 0; i < 2; ++i) {
            int idx = tid + (i << 8);
            int k  = idx >> 5;
            int c4 = (idx & 31) << 2;
            *(float4*)&As[k][c4] =
                *(const float4*)(g_xcat + (size_t)(bb * 256 + k0 + k) * 4096 + p0 + c4);
            int r  = idx >> 2;
            int kq = (idx & 3) << 2;
            float4 vb = *(const float4*)(PW + (size_t)(n0 + r) * 256 + k0 + kq);
            Bs[kq+0][r]=vb.x; Bs[kq+1][r]=vb.y; Bs[kq+2][r]=vb.z; Bs[kq+3][r]=vb.w;
        }
        __syncthreads();
        #pragma unroll
        for (int k = 0; k < 16; ++k) {
            float a[8], b[8];
            *(float4*)&a[0] = *(const float4*)&As[k][tm];
            *(float4*)&a[4] = *(const float4*)&As[k][tm + 4];
            *(float4*)&b[0] = *(const float4*)&Bs[k][tn];
            *(float4*)&b[4] = *(const float4*)&Bs[k][tn + 4];
            #pragma unroll
            for (int i = 0; i < 8; ++i)
                #pragma unroll
                for (int j = 0; j < 8; ++j)
                    acc[i][j] = fmaf(a[i], b[j], acc[i][j]);
        }
        __syncthreads();
    }
    #pragma unroll
    for (int j = 0; j < 8; ++j) {
        int n = n0 + tn + j;
        float pbv = PB[n];
        float* cp = out + (size_t)(bb * 256 + n) * 4096 + p0 + tm;
        float4 c0 = {acc[0][j] + pbv, acc[1][j] + pbv, acc[2][j] + pbv, acc[3][j] + pbv};
        float4 c1 = {acc[4][j] + pbv, acc[5][j] + pbv, acc[6][j] + pbv, acc[7][j] + pbv};
        *(float4*)cp = c0; *(float4*)(cp + 4) = c1;
    }
}

// ---------------- launcher ----------------
extern "C" void kernel_launch(void* const* d_in, const int* in_sizes, int n_in,
                              void* d_out, int out_size) {
    const float* x       = (const float*)d_in[0];
    const float* ln_g    = (const float*)d_in[1];
    const float* ln_b    = (const float*)d_in[2];
    const float* w_qkv   = (const float*)d_in[3];
    const float* proj_w  = (const float*)d_in[4];
    const float* proj_b  = (const float*)d_in[5];
    const float* lepe_w1 = (const float*)d_in[6];
    const float* lepe_b1 = (const float*)d_in[7];
    const float* lepe_w2 = (const float*)d_in[8];
    const float* lepe_b2 = (const float*)d_in[9];
    float* out = (float*)d_out;

    // tuple output layout: out(8388608) | attn1(33554432) | attn2(33554432)
    float* a0 = nullptr; float* a1 = nullptr;
    if (out_size >= 75497472) { a0 = out + 8388608; a1 = a0 + 33554432; }

    const int ATTN_SMEM = 21312 * 4;
    cudaFuncSetAttribute(attn_kernel, cudaFuncAttributeMaxDynamicSharedMemorySize, ATTN_SMEM);

    ln_kernel<<<1024, dim3(32, 32)>>>(x, ln_g, ln_b);
    gemm_qkv<<<dim3(6, 256), 256>>>(w_qkv);
    attn_kernel<<<1024, 256, ATTN_SMEM>>>(lepe_w1, lepe_b1, lepe_w2, lepe_b2, a0, a1);
    gemm_proj<<<dim3(2, 256), 256>>>(proj_w, proj_b, out);
}